// round 1
// baseline (speedup 1.0000x reference)
#include <cuda_runtime.h>
#include <math.h>

#define N_IMG 128
#define N_ANG 285
#define N_DET 183
#define N_T   384

#define PITCH 133           // smem row pitch in floats (133 % 32 = 5 -> conflict-friendly)
#define PROWS 131           // rows -1..129 of padded image
#define SMEM_FLOATS (PROWS * PITCH)
#define SMEM_BYTES  (SMEM_FLOATS * 4)

#define THREADS 384         // 2 t-segments x 192 (>=183 detectors)

__global__ __launch_bounds__(THREADS)
void radon_fwd_kernel(const float* __restrict__ x, float* __restrict__ out) {
    extern __shared__ float simg[];          // padded, pre-scaled image
    __shared__ float part[THREADS];
    __shared__ double trig[2];               // sin, cos

    const int tid = threadIdx.x;
    const int ang = blockIdx.x;
    const int b   = blockIdx.y;

    // Constants (double, matching the numpy reference expressions)
    const double RHO = 20.0 * sqrt(2.0);
    const double DX  = 40.0 / (double)N_IMG;           // 0.3125 exact
    const double DT  = 2.0 * RHO / (double)N_T;
    const float  SCALE = (float)(DT / 12.0);           // fold x/12 and *DT into image

    if (tid == 0) {
        double a = ((double)ang + 0.5) * M_PI / (double)N_ANG;
        trig[0] = sin(a);
        trig[1] = cos(a);
    }

    // Zero the whole padded tile (border must be 0)
    for (int i = tid; i < SMEM_FLOATS; i += THREADS) simg[i] = 0.0f;
    __syncthreads();

    // Fill interior with scaled image
    const float* img = x + (size_t)b * N_IMG * N_IMG;
    for (int i = tid; i < N_IMG * N_IMG; i += THREADS) {
        int r = i >> 7;
        int c = i & 127;
        simg[(r + 1) * PITCH + (c + 1)] = img[i] * SCALE;
    }
    __syncthreads();

    const double dsin = trig[0];
    const double dcos = trig[1];

    const int det = tid % 192;
    const int seg = tid / 192;

    float acc = 0.0f;

    if (det < N_DET) {
        // Per-ray geometry in double (matches reference fp64 coordinate math)
        double s  = -RHO + ((double)det + 0.5) * (2.0 * RHO / (double)N_DET);
        double tb = -RHO + 0.5 * DT;

        double b0d = ((-s * dsin + tb * dcos) + 20.0) / DX - 0.5;  // row coord at k=0
        double st0 = DT * dcos / DX;
        double b1d = (( s * dcos + tb * dsin) + 20.0) / DX - 0.5;  // col coord at k=0
        double st1 = DT * dsin / DX;

        // k-range where both coords lie in (-1, 128); generous +/-1 margin,
        // per-sample clamp + zero border makes extras contribute exactly 0.
        int klo = seg * 192;
        int khi = klo + 192;
        if (khi > N_T) khi = N_T;

        {
            double bases[2] = {b0d, b1d};
            double steps[2] = {st0, st1};
            #pragma unroll
            for (int ax = 0; ax < 2; ++ax) {
                double bs = bases[ax], st = steps[ax];
                if (fabs(st) < 1e-9) {
                    if (bs < -1.0 || bs > 128.0) { klo = khi; }
                } else {
                    double t0 = (-1.0 - bs) / st;
                    double t1 = (128.0 - bs) / st;
                    double lo = fmin(t0, t1), hi = fmax(t0, t1);
                    int kl = (int)floor(lo) - 1;
                    int kh = (int)ceil(hi) + 2;   // exclusive
                    if (kl > klo) klo = kl;
                    if (kh < khi) khi = kh;
                }
            }
        }

        const float b0 = (float)b0d, s0 = (float)st0;
        const float b1 = (float)b1d, s1 = (float)st1;

        float kf = (float)klo;
        #pragma unroll 4
        for (int k = klo; k < khi; ++k, kf += 1.0f) {
            float f0 = fmaf(kf, s0, b0);
            float f1 = fmaf(kf, s1, b1);
            // clamp into padded range: OOB samples hit the zero border with
            // the complementary weight forced to 0 by the clamp
            f0 = fminf(fmaxf(f0, -1.0f), 128.0f);
            f1 = fminf(fmaxf(f1, -1.0f), 128.0f);
            int i = __float2int_rd(f0);
            int j = __float2int_rd(f1);
            float a  = f0 - (float)i;
            float bf = f1 - (float)j;
            const float* p = &simg[(i + 1) * PITCH + (j + 1)];
            float v00 = p[0];
            float v01 = p[1];
            float v10 = p[PITCH];
            float v11 = p[PITCH + 1];
            float top = fmaf(bf, v01 - v00, v00);
            float bot = fmaf(bf, v11 - v10, v10);
            acc = fmaf(a, bot - top, acc + top);
        }
    }

    part[tid] = acc;
    __syncthreads();

    if (tid < N_DET) {
        float r = part[tid] + part[tid + 192];
        out[((size_t)b * N_ANG + ang) * N_DET + tid] = r;
    }
}

extern "C" void kernel_launch(void* const* d_in, const int* in_sizes, int n_in,
                              void* d_out, int out_size) {
    const float* x = (const float*)d_in[0];
    float* out = (float*)d_out;
    cudaFuncSetAttribute(radon_fwd_kernel,
                         cudaFuncAttributeMaxDynamicSharedMemorySize, SMEM_BYTES);
    dim3 grid(N_ANG, 8);
    radon_fwd_kernel<<<grid, THREADS, SMEM_BYTES>>>(x, out);
}

// round 2
// speedup vs baseline: 1.8943x; 1.8943x over previous
#include <cuda_runtime.h>
#include <cuda_fp16.h>
#include <math.h>

#define N_IMG 128
#define N_ANG 285
#define N_DET 183
#define N_T   384

#define PITCH2 133          // smem row pitch in half2 entries (stride 5 mod 32 banks)
#define PROWS  131          // padded rows: original -1..129
#define SMEM_H2    (PROWS * PITCH2)
#define SMEM_BYTES (SMEM_H2 * 4)

#define THREADS 384         // 2 t-segments x 192 (>=183 detectors)

__global__ __launch_bounds__(THREADS)
void radon_fwd_kernel(const float* __restrict__ x, float* __restrict__ out) {
    extern __shared__ __half2 simg[];   // padded image pair: .x = batch A, .y = batch B
    __shared__ float2 part[THREADS];
    __shared__ double trig[2];          // sin, cos

    const int tid = threadIdx.x;
    const int ang = blockIdx.x;
    const int bp  = blockIdx.y;         // batch pair index (0..3)

    const double RHO = 20.0 * sqrt(2.0);
    const double DX  = 0.3125;                       // 40/128 exact
    const double DT  = 2.0 * RHO / (double)N_T;
    const float  SCALE = (float)(DT / 12.0);         // applied once at the end

    if (tid == 0) {
        double a = ((double)ang + 0.5) * M_PI / (double)N_ANG;
        trig[0] = sin(a);
        trig[1] = cos(a);
    }

    // Zero the padded tile (border must be exactly 0)
    for (int i = tid; i < SMEM_H2; i += THREADS)
        simg[i] = __floats2half2_rn(0.0f, 0.0f);
    __syncthreads();

    // Interleave the two batch images as half2 (unscaled)
    const float* iA = x + (size_t)(2 * bp) * N_IMG * N_IMG;
    const float* iB = iA + N_IMG * N_IMG;
    for (int i = tid; i < N_IMG * N_IMG; i += THREADS) {
        int r = i >> 7;
        int c = i & 127;
        simg[(r + 1) * PITCH2 + (c + 1)] = __floats2half2_rn(iA[i], iB[i]);
    }
    __syncthreads();

    const double dsin = trig[0];
    const double dcos = trig[1];

    const int det = tid % 192;
    const int seg = tid / 192;

    float accA = 0.0f, accB = 0.0f;

    if (det < N_DET) {
        // Per-ray geometry in double (matches reference fp64 coordinate math).
        // Work directly in PADDED index space: padded = original + 1.
        double s  = -RHO + ((double)det + 0.5) * (2.0 * RHO / (double)N_DET);
        double tb = -RHO + 0.5 * DT;

        double b0d = ((-s * dsin + tb * dcos) + 20.0) / DX + 0.5;  // padded row @ k=0
        double st0 = DT * dcos / DX;
        double b1d = (( s * dcos + tb * dsin) + 20.0) / DX + 0.5;  // padded col @ k=0
        double st1 = DT * dsin / DX;

        // k-range with both padded coords in [EPS, 129-EPS]; guarantees
        // i in [0,129], i+1 <= 130 -> no clamps needed in the hot loop.
        // Excluded boundary samples have weight <= ~2e-4 -> negligible.
        const double EPS = 2e-4;
        int klo = seg * 192;
        int khi = klo + 192;
        if (khi > N_T) khi = N_T;
        {
            double bases[2] = {b0d, b1d};
            double steps[2] = {st0, st1};
            #pragma unroll
            for (int ax = 0; ax < 2; ++ax) {
                double bs = bases[ax], st = steps[ax];
                if (fabs(st) < 1e-9) {
                    if (bs < EPS || bs > 129.0 - EPS) klo = khi;
                } else {
                    double t0 = (EPS - bs) / st;
                    double t1 = ((129.0 - EPS) - bs) / st;
                    double lo = fmin(t0, t1), hi = fmax(t0, t1);
                    int kl = (int)ceil(lo);
                    int kh = (int)floor(hi) + 1;   // exclusive
                    if (kl > klo) klo = kl;
                    if (kh < khi) khi = kh;
                }
            }
        }

        const float b0 = (float)b0d, s0 = (float)st0;
        const float b1 = (float)b1d, s1 = (float)st1;

        float kf = (float)klo;
        #pragma unroll 4
        for (int k = klo; k < khi; ++k, kf += 1.0f) {
            float f0 = fmaf(kf, s0, b0);
            float f1 = fmaf(kf, s1, b1);
            float fl0 = floorf(f0);
            float fl1 = floorf(f1);
            float a  = f0 - fl0;
            float bb = f1 - fl1;
            int i = (int)fl0;
            int j = (int)fl1;
            const __half2* p = &simg[i * PITCH2 + j];
            __half2 v00 = p[0];
            __half2 v01 = p[1];
            __half2 v10 = p[PITCH2];
            __half2 v11 = p[PITCH2 + 1];
            __half2 b2 = __float2half2_rn(bb);
            __half2 a2 = __float2half2_rn(a);
            __half2 top = __hfma2(b2, __hsub2(v01, v00), v00);
            __half2 bot = __hfma2(b2, __hsub2(v11, v10), v10);
            __half2 r2  = __hfma2(a2, __hsub2(bot, top), top);
            float2 rf = __half22float2(r2);
            accA += rf.x;
            accB += rf.y;
        }
    }

    part[tid] = make_float2(accA, accB);
    __syncthreads();

    if (tid < N_DET) {
        float2 p0 = part[tid];
        float2 p1 = part[tid + 192];
        float rA = (p0.x + p1.x) * SCALE;
        float rB = (p0.y + p1.y) * SCALE;
        size_t baseA = ((size_t)(2 * bp)     * N_ANG + ang) * N_DET + tid;
        size_t baseB = ((size_t)(2 * bp + 1) * N_ANG + ang) * N_DET + tid;
        out[baseA] = rA;
        out[baseB] = rB;
    }
}

extern "C" void kernel_launch(void* const* d_in, const int* in_sizes, int n_in,
                              void* d_out, int out_size) {
    const float* x = (const float*)d_in[0];
    float* out = (float*)d_out;
    cudaFuncSetAttribute(radon_fwd_kernel,
                         cudaFuncAttributeMaxDynamicSharedMemorySize, SMEM_BYTES);
    dim3 grid(N_ANG, 4);
    radon_fwd_kernel<<<grid, THREADS, SMEM_BYTES>>>(x, out);
}